// round 10
// baseline (speedup 1.0000x reference)
#include <cuda_runtime.h>

// Potts energy: out[b] = sum_{i<=j} W[i,j] * [(1-x_i)(1-x_j) + x_i*x_j]
//             = wsum - sum_i rs_i x_i - sum_j cs_j x_j + 2 sum_{i<=j} W_ij x_i x_j
// 64x64 tiles over upper triangle, each split into 2 i-halves -> 272 CTAs.
// R10: no V staging (registers straight from global); W kept i-major in smem
// (coalesced STS.128 staging, warp-uniform broadcast LDS.128 in mainloop).

#define Bb      128
#define Nn      1024
#define T       64
#define HI      32
#define NT      16
#define NCTAS   272
#define WDS     66      // Wd row stride in u64 (even -> 16B-aligned rows)
#define THREADS 256

__device__ float        g_accum[Bb];
__device__ unsigned int g_count;

__device__ __forceinline__ unsigned long long pack2(float lo, float hi) {
    unsigned long long r;
    asm("mov.b64 %0, {%1, %2};" : "=l"(r) : "f"(lo), "f"(hi));
    return r;
}
__device__ __forceinline__ void unpack2(unsigned long long v, float& lo, float& hi) {
    asm("mov.b64 {%0, %1}, %2;" : "=f"(lo), "=f"(hi) : "l"(v));
}
__device__ __forceinline__ unsigned long long fma2(unsigned long long a,
                                                   unsigned long long b,
                                                   unsigned long long c) {
    unsigned long long d;
    asm("fma.rn.f32x2 %0, %1, %2, %3;" : "=l"(d) : "l"(a), "l"(b), "l"(c));
    return d;
}
__device__ __forceinline__ unsigned long long add2(unsigned long long a,
                                                   unsigned long long b) {
    unsigned long long d;
    asm("add.rn.f32x2 %0, %1, %2;" : "=l"(d) : "l"(a), "l"(b));
    return d;
}

extern __shared__ unsigned long long sm[];

__global__ void __launch_bounds__(THREADS, 2)
potts_k(const float* __restrict__ V,   // [128,1024]
        const float* __restrict__ W,   // [1024,1024]
        float* __restrict__ out)       // [128]
{
    unsigned long long* Wd   = sm;              // [HI i][WDS] (w,w) dup, masked, i-major
    unsigned long long* cs2n = Wd + HI * WDS;   // [64] (-cs,-cs)
    unsigned long long* rs2n = cs2n + 64;       // [32] (-rs,-rs)
    unsigned long long* red  = rs2n + 32;       // [4][64]
    float* csp  = (float*)(red + 256);          // [64][4]
    float* rsp  = csp + 256;                    // [32][8]
    float* wsum = rsp + 256;                    // [1]

    const int tid  = threadIdx.x;
    const int warp = tid >> 5;
    const int lane = tid & 31;
    const int jg   = warp >> 1;                 // 0..3 -> 16 j each
    const int bpg  = (warp & 1) * 32 + lane;    // 0..63 batch pair
    const int jbase = jg * 16;

    // ---- CTA -> (tile, i-half) ----
    int k = blockIdx.x >> 1;
    const int h = blockIdx.x & 1;
    int bi = 0;
    while (k >= NT - bi) { k -= NT - bi; bi++; }
    const int bj   = bi + k;
    const int gi0h = bi * T + h * HI;
    const int gj0  = bj * T;
    const bool diag = (bi == bj);
    const int iofs = h * HI;

    // ---- preload x straight from global into packed registers ----
    // (issued first so LDG latency overlaps W staging)
    const float* vr0 = V + (size_t)(2 * bpg) * Nn;
    const float* vr1 = vr0 + Nn;
    unsigned long long x2[HI];                  // (x_b0, x_b1) for i-rows
    #pragma unroll
    for (int q = 0; q < 8; q++) {
        float4 a = *(const float4*)(vr0 + gi0h + q * 4);
        float4 c = *(const float4*)(vr1 + gi0h + q * 4);
        x2[q * 4 + 0] = pack2(a.x, c.x);
        x2[q * 4 + 1] = pack2(a.y, c.y);
        x2[q * 4 + 2] = pack2(a.z, c.z);
        x2[q * 4 + 3] = pack2(a.w, c.w);
    }
    unsigned long long xj2[16];                 // (x_b0, x_b1) for this thread's 16 j
    #pragma unroll
    for (int q = 0; q < 4; q++) {
        float4 a = *(const float4*)(vr0 + gj0 + jbase + q * 4);
        float4 c = *(const float4*)(vr1 + gj0 + jbase + q * 4);
        xj2[q * 4 + 0] = pack2(a.x, c.x);
        xj2[q * 4 + 1] = pack2(a.y, c.y);
        xj2[q * 4 + 2] = pack2(a.z, c.z);
        xj2[q * 4 + 3] = pack2(a.w, c.w);
    }

    // ---- stage W half-tile i-major, dup (w,w), masked: coalesced STS.128 ----
    #pragma unroll
    for (int it = 0; it < 2; it++) {
        int idx = it * THREADS + tid;           // 512 float4
        int ii  = idx >> 4;                     // 0..31 local i
        int qq  = idx & 15;
        float4 w = *(const float4*)(W + (size_t)(gi0h + ii) * Nn + gj0 + qq * 4);
        int gr = iofs + ii, j0 = qq * 4;
        if (diag) {
            if (gr > j0 + 0) w.x = 0.0f;
            if (gr > j0 + 1) w.y = 0.0f;
            if (gr > j0 + 2) w.z = 0.0f;
            if (gr > j0 + 3) w.w = 0.0f;
        }
        ulonglong2* dst = (ulonglong2*)(Wd + ii * WDS + j0);
        dst[0] = make_ulonglong2(pack2(w.x, w.x), pack2(w.y, w.y));
        dst[1] = make_ulonglong2(pack2(w.z, w.z), pack2(w.w, w.w));
    }
    __syncthreads();

    // ---- cooperative col/row sums of masked half (lo floats of Wd) ----
    {
        const float* Wlo = (const float*)Wd;
        int jj = tid >> 2, c = tid & 3;         // cs partial: 64 j x 4 chunks of 8 i
        float pc = 0.0f;
        #pragma unroll
        for (int t = 0; t < 8; t++)
            pc += Wlo[((c * 8 + t) * WDS + jj) * 2];
        csp[jj * 4 + c] = pc;
        int i2 = tid >> 3, c2 = tid & 7;        // rs partial: 32 i x 8 chunks of 8 j
        float pr = 0.0f;
        #pragma unroll
        for (int t = 0; t < 8; t++)
            pr += Wlo[(i2 * WDS + c2 * 8 + t) * 2];
        rsp[i2 * 8 + c2] = pr;
    }
    __syncthreads();
    if (tid < 64) {
        float s = csp[tid * 4] + csp[tid * 4 + 1] + csp[tid * 4 + 2] + csp[tid * 4 + 3];
        cs2n[tid] = pack2(-s, -s);
    } else if (tid < 96) {
        int i = tid - 64;
        float s = 0.0f;
        #pragma unroll
        for (int c = 0; c < 8; c++) s += rsp[i * 8 + c];
        rs2n[i] = pack2(-s, -s);
    }
    __syncthreads();
    if (warp == 0) {
        const float* cslo = (const float*)cs2n;
        float v = cslo[lane * 2] + cslo[(lane + 32) * 2];
        #pragma unroll
        for (int o = 16; o > 0; o >>= 1) v += __shfl_down_sync(0xffffffffu, v, o);
        if (lane == 0) wsum[0] = -v;            // cs2n holds negated sums
    }

    // ---- mainloop: 8 j-pairs; W via warp-uniform broadcast LDS.128 ----
    const unsigned long long two2 = pack2(2.0f, 2.0f);
    unsigned long long q = 0;
    #pragma unroll 2
    for (int jp = 0; jp < 8; jp++) {
        const int j = jbase + jp * 2;           // even -> 16B-aligned ulonglong2
        unsigned long long a0 = 0, a1 = 0, b0 = 0, b1 = 0;
        #pragma unroll
        for (int i = 0; i < HI; i += 2) {
            ulonglong2 wA = *(const ulonglong2*)(Wd + i * WDS + j);        // bcast
            ulonglong2 wB = *(const ulonglong2*)(Wd + (i + 1) * WDS + j);  // bcast
            a0 = fma2(wA.x, x2[i],     a0);     // chain for j
            b0 = fma2(wA.y, x2[i],     b0);     // chain for j+1
            a1 = fma2(wB.x, x2[i + 1], a1);
            b1 = fma2(wB.y, x2[i + 1], b1);
        }
        ulonglong2 csj = *(const ulonglong2*)(cs2n + j);                   // bcast
        unsigned long long tj  = fma2(add2(a0, a1), two2, csj.x);
        unsigned long long tj1 = fma2(add2(b0, b1), two2, csj.y);
        q = fma2(xj2[jp * 2 + 0], tj,  q);
        q = fma2(xj2[jp * 2 + 1], tj1, q);
    }

    // ---- fold -rs_i * x_bi (each jg covers its 8 i-rows) ----
    #pragma unroll
    for (int t = 0; t < 8; t++) {
        int i = jg * 8 + t;
        q = fma2(rs2n[i], x2[i], q);
    }

    red[jg * 64 + bpg] = q;                     // bijective -> no collisions
    __syncthreads();

    // ---- final per-batch-pair reduction + global accumulate ----
    if (tid < 64) {
        unsigned long long s = add2(add2(red[tid], red[64 + tid]),
                                    add2(red[128 + tid], red[192 + tid]));
        float e0, e1;
        unpack2(s, e0, e1);
        float ws = wsum[0];
        atomicAdd(&g_accum[2 * tid + 0], e0 + ws);
        atomicAdd(&g_accum[2 * tid + 1], e1 + ws);
    }
    __threadfence();
    __syncthreads();

    __shared__ bool last;
    if (tid == 0) last = (atomicAdd(&g_count, 1u) == NCTAS - 1);
    __syncthreads();

    if (last) {
        __threadfence();
        if (tid < Bb) out[tid] = atomicExch(&g_accum[tid], 0.0f);
        if (tid == 0) atomicExch(&g_count, 0u);
    }
}

extern "C" void kernel_launch(void* const* d_in, const int* in_sizes, int n_in,
                              void* d_out, int out_size)
{
    const float* V = (const float*)d_in[0];
    const float* W = (const float*)d_in[1];
    float* out = (float*)d_out;

    const int smem_bytes = (HI * WDS + 64 + 32 + 256) * 8
                         + (256 + 256 + 4) * 4;   // ~21.8 KB
    cudaFuncSetAttribute(potts_k, cudaFuncAttributeMaxDynamicSharedMemorySize,
                         smem_bytes);

    potts_k<<<NCTAS, THREADS, smem_bytes>>>(V, W, out);
}

// round 11
// speedup vs baseline: 2.2851x; 2.2851x over previous
#include <cuda_runtime.h>

// Potts energy: out[b] = sum_{i<=j} W[i,j] * [(1-x_i)(1-x_j) + x_i*x_j]
// Per masked tile row i:  E_i(b) = (1-x_bi)*u_i + t_i(b)*(2*x_bi - 1)
//   t_i(b) = sum_j U_ij x_bj,   u_i = sum_j U_ij   (batch independent)
// 64x64 tiles over upper triangle, split into 2 i-halves -> 272 CTAs (~2/SM).
// W stays i-major (coalesced staging, broadcast reads). Scalar FFMA only.

#define Bb      128
#define Nn      1024
#define T       64
#define HI      32
#define NT      16
#define NCTAS   272
#define WDS     68      // Wd row stride (floats): i*68 -> 16B aligned rows
#define VIS     129     // Vi stride (conflict-free b-indexed reads)
#define VJS     129     // Vj stride
#define THREADS 256

__device__ float        g_accum[Bb];
__device__ unsigned int g_count;

extern __shared__ float smf[];

__global__ void __launch_bounds__(THREADS, 2)
potts_k(const float* __restrict__ V,   // [128,1024]
        const float* __restrict__ W,   // [1024,1024]
        float* __restrict__ out)       // [128]
{
    float* Wd  = smf;                  // [32 i][WDS]  masked half-tile, i-major
    float* Vi  = Wd + HI * WDS;        // [32 i][VIS]  x transposed [i][b]
    float* Vj  = Vi + HI * VIS;        // [64 j][VJS]  x transposed [j][b]
    float* u   = Vj + T * VJS;         // [32] row sums
    float* usp = u + HI;               // [32][8] partials
    float* red = usp + 256;            // [2][128]

    const int tid = threadIdx.x;
    const int b   = tid & 127;         // batch
    const int g   = tid >> 7;          // j-half (warp-uniform)

    // ---- CTA -> (tile, i-half) ----
    int k = blockIdx.x >> 1;
    const int h = blockIdx.x & 1;
    int bi = 0;
    while (k >= NT - bi) { k -= NT - bi; bi++; }
    const int bj   = bi + k;
    const int gi0h = bi * T + h * HI;
    const int gj0  = bj * T;
    const bool diag = (bi == bj);
    const int iofs = h * HI;

    // ---- stage W half-tile i-major, masked (512 float4, coalesced both ways) ----
    #pragma unroll
    for (int it = 0; it < 2; it++) {
        int idx = it * THREADS + tid;
        int ii  = idx >> 4;                 // local i (0..31)
        int q   = idx & 15;
        float4 w = *(const float4*)(W + (size_t)(gi0h + ii) * Nn + gj0 + q * 4);
        int gr = iofs + ii, j0 = q * 4;
        if (diag) {
            if (gr > j0 + 0) w.x = 0.0f;
            if (gr > j0 + 1) w.y = 0.0f;
            if (gr > j0 + 2) w.z = 0.0f;
            if (gr > j0 + 3) w.w = 0.0f;
        }
        *(float4*)(Wd + ii * WDS + j0) = w;
    }

    // ---- stage Vi [32 i][128 b] transposed (1024 float4 coalesced LDG) ----
    #pragma unroll
    for (int it = 0; it < 4; it++) {
        int idx = it * THREADS + tid;
        int bb  = idx >> 3;                 // 0..127
        int q   = idx & 7;
        float4 a = *(const float4*)(V + (size_t)bb * Nn + gi0h + q * 4);
        Vi[(q * 4 + 0) * VIS + bb] = a.x;
        Vi[(q * 4 + 1) * VIS + bb] = a.y;
        Vi[(q * 4 + 2) * VIS + bb] = a.z;
        Vi[(q * 4 + 3) * VIS + bb] = a.w;
    }

    // ---- stage Vj [64 j][128 b] transposed (2048 float4 coalesced LDG) ----
    #pragma unroll
    for (int it = 0; it < 8; it++) {
        int idx = it * THREADS + tid;
        int bb  = idx >> 4;
        int q   = idx & 15;
        float4 c = *(const float4*)(V + (size_t)bb * Nn + gj0 + q * 4);
        Vj[(q * 4 + 0) * VJS + bb] = c.x;
        Vj[(q * 4 + 1) * VJS + bb] = c.y;
        Vj[(q * 4 + 2) * VJS + bb] = c.z;
        Vj[(q * 4 + 3) * VJS + bb] = c.w;
    }
    __syncthreads();

    // ---- cooperative row sums u_i over masked half (contiguous reads) ----
    {
        int i2 = tid >> 3, c2 = tid & 7;
        float pr = 0.0f;
        #pragma unroll
        for (int t = 0; t < 8; t++) pr += Wd[i2 * WDS + c2 * 8 + t];
        usp[i2 * 8 + c2] = pr;
    }
    __syncthreads();
    if (tid < HI) {
        float s = 0.0f;
        #pragma unroll
        for (int c = 0; c < 8; c++) s += usp[tid * 8 + c];
        u[tid] = s;
    }
    __syncthreads();

    // ---- preload this thread's 32 x_j into registers (conflict-free) ----
    float vj[32];
    #pragma unroll
    for (int jj = 0; jj < 32; jj++) vj[jj] = Vj[(g * 32 + jj) * VJS + b];

    // ---- mainloop: serial i; W row slice = warp-uniform broadcast LDS.128 ----
    float qacc = 0.0f;
    #pragma unroll 4
    for (int i = 0; i < HI; i++) {
        const float4* wr = (const float4*)(Wd + i * WDS + g * 32);
        float t0 = 0.0f, t1 = 0.0f, t2 = 0.0f, t3 = 0.0f;
        #pragma unroll
        for (int kk = 0; kk < 8; kk++) {
            float4 w = wr[kk];
            t0 = fmaf(w.x, vj[4 * kk + 0], t0);
            t1 = fmaf(w.y, vj[4 * kk + 1], t1);
            t2 = fmaf(w.z, vj[4 * kk + 2], t2);
            t3 = fmaf(w.w, vj[4 * kk + 3], t3);
        }
        float t  = (t0 + t1) + (t2 + t3);
        float vi = Vi[i * VIS + b];                 // conflict-free LDS.32
        qacc = fmaf(t, 2.0f * vi - 1.0f, qacc);
    }

    // ---- linear term (g==0 warps only; warp-uniform branch) ----
    if (g == 0) {
        float l0 = 0.0f, l1 = 0.0f;
        #pragma unroll 8
        for (int i = 0; i < HI; i += 2) {
            l0 = fmaf(u[i],     1.0f - Vi[i * VIS + b],       l0);
            l1 = fmaf(u[i + 1], 1.0f - Vi[(i + 1) * VIS + b], l1);
        }
        qacc += l0 + l1;
    }

    red[g * 128 + b] = qacc;
    __syncthreads();

    // ---- per-batch reduction + global accumulate ----
    if (tid < Bb) {
        float e = red[tid] + red[128 + tid];
        atomicAdd(&g_accum[tid], e);
    }
    __threadfence();
    __syncthreads();

    __shared__ bool last;
    if (tid == 0) last = (atomicAdd(&g_count, 1u) == NCTAS - 1);
    __syncthreads();

    if (last) {
        __threadfence();
        if (tid < Bb) out[tid] = atomicExch(&g_accum[tid], 0.0f);
        if (tid == 0) atomicExch(&g_count, 0u);
    }
}

extern "C" void kernel_launch(void* const* d_in, const int* in_sizes, int n_in,
                              void* d_out, int out_size)
{
    const float* V = (const float*)d_in[0];
    const float* W = (const float*)d_in[1];
    float* out = (float*)d_out;

    const int smem_bytes = (HI * WDS + HI * VIS + T * VJS + HI + 256 + 256)
                         * (int)sizeof(float);   // 60416 B -> 2 CTAs/SM fits
    cudaFuncSetAttribute(potts_k, cudaFuncAttributeMaxDynamicSharedMemorySize,
                         smem_bytes);

    potts_k<<<NCTAS, THREADS, smem_bytes>>>(V, W, out);
}